// round 12
// baseline (speedup 1.0000x reference)
#include <cuda_runtime.h>
#include <cuda_fp16.h>
#include <cstdint>

#define N_NODES 100000
#define E_EDGES 640000

// ---------------------------------------------------------------------------
// Global scratch
// ---------------------------------------------------------------------------
__device__ float  g_xw[(size_t)N_NODES * 128];     // x @ Wn
__device__ __half g_axw_h[(size_t)N_NODES * 128];  // fp16 shadow of axw
__device__ int    g_idx64;                          // edge_index dtype flag

// ---------------------------------------------------------------------------
// Helpers
// ---------------------------------------------------------------------------
__device__ __forceinline__ uint32_t smem_u32(const void* p) {
    uint32_t a;
    asm("{ .reg .u64 t; cvta.to.shared.u64 t, %1; cvt.u32.u64 %0, t; }"
        : "=r"(a) : "l"(p));
    return a;
}

__device__ __forceinline__ void mma_f16(float* d, const uint32_t* a, const uint32_t* b) {
    asm volatile(
        "mma.sync.aligned.m16n8k16.row.col.f32.f16.f16.f32 "
        "{%0,%1,%2,%3}, {%4,%5,%6,%7}, {%8,%9}, {%0,%1,%2,%3};"
        : "+f"(d[0]), "+f"(d[1]), "+f"(d[2]), "+f"(d[3])
        : "r"(a[0]), "r"(a[1]), "r"(a[2]), "r"(a[3]), "r"(b[0]), "r"(b[1]));
}

__device__ __forceinline__ void ldsm_x4(uint32_t* r, uint32_t addr) {
    asm volatile("ldmatrix.sync.aligned.m8n8.x4.shared.b16 {%0,%1,%2,%3}, [%4];"
                 : "=r"(r[0]), "=r"(r[1]), "=r"(r[2]), "=r"(r[3]) : "r"(addr));
}
__device__ __forceinline__ void ldsm_x4t(uint32_t* r, uint32_t addr) {
    asm volatile("ldmatrix.sync.aligned.m8n8.x4.trans.shared.b16 {%0,%1,%2,%3}, [%4];"
                 : "=r"(r[0]), "=r"(r[1]), "=r"(r[2]), "=r"(r[3]) : "r"(addr));
}

// ---------------------------------------------------------------------------
// edge_index dtype detection (int32 vs int64)
// ---------------------------------------------------------------------------
__global__ void detect_idx_kernel(const void* __restrict__ eidx) {
    if (threadIdx.x == 0 && blockIdx.x == 0) {
        const unsigned long long* p = (const unsigned long long*)eidx;
        int ok = 1;
        #pragma unroll 1
        for (int i = 0; i < 64; i++)
            if (p[i] >= (unsigned long long)N_NODES) { ok = 0; break; }
        g_idx64 = ok;
    }
}

__device__ __forceinline__ long ld_idx(const void* __restrict__ p, long i) {
    if (g_idx64) return (long)((const long long*)p)[i];
    return (long)((const int*)p)[i];
}

__global__ void zero4_kernel(float4* __restrict__ p, int n4) {
    int i = blockIdx.x * blockDim.x + threadIdx.x;
    if (i < n4) p[i] = make_float4(0.f, 0.f, 0.f, 0.f);
}

// axw (fp32) -> fp16 shadow for low-traffic gathers
__global__ void tohalf_kernel(const float2* __restrict__ in, __half2* __restrict__ outp, int n2) {
    int i = blockIdx.x * blockDim.x + threadIdx.x;
    if (i < n2) {
        float2 v = in[i];
        outp[i] = __floats2half2_rn(v.x, v.y);
    }
}

// ---------------------------------------------------------------------------
// Persistent plain fp16 GEMM, 64-row tiles: C[M x 128] = A[M x K] @ W[K x 128]
// 8 warps in 2(row) x 4(col); warp tile 32x32. Cross-chunk A double-buffering.
// Smem: [0, K*256) W fp16 swizzled | + 2 x 16KB A bufs.
// Sized for cross-kernel co-residency: ew (64KB) + xw (96KB) share an SM.
// ---------------------------------------------------------------------------
template<int KCH>
__global__ __launch_bounds__(256, 2)
void gemm_kernel(const float* __restrict__ A, const float* __restrict__ W,
                 float* __restrict__ C, int M) {
    constexpr int K = KCH * 128;
    constexpr uint32_t OFF_A = (uint32_t)K * 256;

    extern __shared__ __align__(128) char smem[];
    const uint32_t sb = smem_u32(smem);
    const int tid = threadIdx.x, lane = tid & 31, wid = tid >> 5;
    const int wr = wid & 1, wc = wid >> 1;

    // W load (single fp16) into swizzled smem (once)
    for (int p = tid; p < K * 64; p += 256) {
        int k = p >> 6, n = (p & 63) * 2;
        float2 wv = *(const float2*)(W + (long)k * 128 + n);
        __half2 hp = __floats2half2_rn(wv.x, wv.y);
        uint32_t off = (uint32_t)k * 256 +
                       ((((uint32_t)n >> 3) ^ ((uint32_t)k & 7)) << 4) + ((n & 7) << 1);
        *(__half2*)(smem + off) = hp;
    }

    const int ntiles = (M + 63) >> 6;
    const int G = gridDim.x;
    float2 pref[16];

    auto prefetch = [&](int t, int kc) {
        #pragma unroll
        for (int i = 0; i < 16; i++) {
            int p = i * 256 + tid;
            int r = p >> 6, pc = p & 63;
            long row = (long)t * 64 + r;
            float2 v = make_float2(0.f, 0.f);
            if (row < M) v = __ldcs((const float2*)(A + row * (long)K + kc * 128 + pc * 2));
            pref[i] = v;
        }
    };
    auto store_buf = [&](int b) {
        #pragma unroll
        for (int i = 0; i < 16; i++) {
            int p = i * 256 + tid;
            int r = p >> 6, col = (p & 63) * 2;
            __half2 hp = __floats2half2_rn(pref[i].x, pref[i].y);
            uint32_t off = (uint32_t)r * 256 +
                           ((((uint32_t)col >> 3) ^ ((uint32_t)r & 7)) << 4) +
                           ((col & 7) << 1);
            *(__half2*)(smem + OFF_A + (uint32_t)b * 16384 + off) = hp;
        }
    };

    int tile = blockIdx.x;
    if (tile < ntiles) {
        prefetch(tile, 0);
        store_buf(0);
        int nt = tile, nkc = 1;
        if (KCH == 1) { nt = tile + G; nkc = 0; }
        if (nt < ntiles) prefetch(nt, nkc);
    }
    __syncthreads();

    int cur = 0;
    for (; tile < ntiles; tile += G) {
        float acc[2][4][4];
        #pragma unroll
        for (int m = 0; m < 2; m++)
            #pragma unroll
            for (int nb = 0; nb < 4; nb++)
                #pragma unroll
                for (int c = 0; c < 4; c++) acc[m][nb][c] = 0.f;

        for (int kc = 0; kc < KCH; kc++) {
            int nt1 = tile, nkc1 = kc + 1;
            if (nkc1 == KCH) { nkc1 = 0; nt1 = tile + G; }
            if (nt1 < ntiles) store_buf(cur ^ 1);
            int nt2 = nt1, nkc2 = nkc1 + 1;
            if (nkc2 == KCH) { nkc2 = 0; nt2 = nt1 + G; }
            if (nt2 < ntiles) prefetch(nt2, nkc2);

            const uint32_t abase = sb + OFF_A + (uint32_t)cur * 16384;
            #pragma unroll
            for (int s = 0; s < 8; s++) {
                uint32_t a[2][4];
                #pragma unroll
                for (int m = 0; m < 2; m++) {
                    uint32_t r = (uint32_t)(wr * 32 + m * 16 + (lane & 15));
                    uint32_t ch = (uint32_t)(s * 2 + (lane >> 4));
                    ldsm_x4(a[m], abase + r * 256 + (((ch ^ (r & 7)) << 4)));
                }
                uint32_t bh[2][4];
                #pragma unroll
                for (int p4 = 0; p4 < 2; p4++) {
                    uint32_t k = (uint32_t)(kc * 128 + s * 16 + (lane & 15));
                    uint32_t nch = (uint32_t)(wc * 4 + p4 * 2 + (lane >> 4));
                    ldsm_x4t(bh[p4], sb + k * 256 + (((nch ^ (k & 7)) << 4)));
                }
                #pragma unroll
                for (int m = 0; m < 2; m++)
                    #pragma unroll
                    for (int p4 = 0; p4 < 2; p4++)
                        #pragma unroll
                        for (int h = 0; h < 2; h++)
                            mma_f16(acc[m][p4 * 2 + h], a[m], &bh[p4][2 * h]);
            }
            if (kc < KCH - 1) { __syncthreads(); cur ^= 1; }
        }

        // epilogue: streamed C store
        #pragma unroll
        for (int j = 0; j < 4; j++) {
            const int m = j >> 1, cp = (j & 1) * 2;
            const int r = wr * 32 + m * 16 + (lane >> 2) + ((j & 1) ? 8 : 0);
            long grow = (long)tile * 64 + r;
            if (grow < M) {
                float* crow = C + grow * 128 + wc * 32 + (lane & 3) * 2;
                #pragma unroll
                for (int nb = 0; nb < 4; nb++)
                    __stcs((float2*)(crow + nb * 8),
                           make_float2(acc[m][nb][cp], acc[m][nb][cp + 1]));
            }
        }
        __syncthreads();    // publishes staged A buf for next tile
        cur ^= 1;
    }
}

// ---------------------------------------------------------------------------
// Scatter-add: axw[dst] += xw[src]  (warp per edge, vector reduction)
// ---------------------------------------------------------------------------
__global__ void scatter_kernel(const void* __restrict__ eidx,
                               const float* __restrict__ xw,
                               float* __restrict__ axw) {
    long t = (long)blockIdx.x * blockDim.x + threadIdx.x;
    if (t >= (long)E_EDGES * 32) return;
    long e = t >> 5;
    int  q = (int)(t & 31) * 4;
    long src = ld_idx(eidx, e);
    long dst = ld_idx(eidx, (long)E_EDGES + e);
    float4 v = *(const float4*)&xw[src * 128 + q];
    float* o = &axw[dst * 128 + q];
    asm volatile("red.global.add.v4.f32 [%0], {%1, %2, %3, %4};"
                 :: "l"(o), "f"(v.x), "f"(v.y), "f"(v.z), "f"(v.w) : "memory");
}

// ---------------------------------------------------------------------------
// DistMult scores: warp per edge; ew row streamed fp32, h/t rows from the
// fp16 axw shadow (full row = 256B, one coalesced 8B load per lane).
// ---------------------------------------------------------------------------
__global__ __launch_bounds__(256)
void scores_kernel(const void* __restrict__ eidx,
                   const __half* __restrict__ axw_h,
                   const float* __restrict__ ew,
                   const float* __restrict__ tcl,
                   const float* __restrict__ lw,
                   float* __restrict__ scores) {
    long t = (long)blockIdx.x * blockDim.x + threadIdx.x;
    long e = t >> 5;
    if (e >= E_EDGES) return;
    int lane = (int)(t & 31);
    long src = ld_idx(eidx, e);
    long dst = ld_idx(eidx, (long)E_EDGES + e);
    float4 wv = __ldcs((const float4*)(ew + e * 128) + lane);
    uint2 hraw = *(const uint2*)(axw_h + src * 128 + lane * 4);
    uint2 traw = *(const uint2*)(axw_h + dst * 128 + lane * 4);
    float2 hf0 = __half22float2(*(__half2*)&hraw.x);
    float2 hf1 = __half22float2(*(__half2*)&hraw.y);
    float2 tf0 = __half22float2(*(__half2*)&traw.x);
    float2 tf1 = __half22float2(*(__half2*)&traw.y);
    float part = fmaf(wv.x * hf0.x, tf0.x,
                 fmaf(wv.y * hf0.y, tf0.y,
                 fmaf(wv.z * hf1.x, tf1.x, wv.w * hf1.y * tf1.y)));
    #pragma unroll
    for (int o = 16; o > 0; o >>= 1)
        part += __shfl_xor_sync(0xFFFFFFFFu, part, o);
    if (lane == 0) scores[e] = part * tcl[e] * lw[0];
}

// ---------------------------------------------------------------------------
// Launch: dual-stream overlap.
//   s0: detect -> zero -> xw -> scatter -> tohalf -> (join) -> scores
//   s1: ew GEMM (independent of everything; forked at entry)
// ---------------------------------------------------------------------------
extern "C" void kernel_launch(void* const* d_in, const int* in_sizes, int n_in,
                              void* d_out, int out_size) {
    const float* x    = (const float*)d_in[0];   // [N, 256]
    const float* ea   = (const float*)d_in[1];   // [E, 128]
    const float* tc   = (const float*)d_in[2];   // [E]
    const float* wn   = (const float*)d_in[3];   // [256, 128]
    const float* we   = (const float*)d_in[4];   // [128, 128]
    const float* lw   = (const float*)d_in[5];   // [1]
    const void*  eidx = d_in[6];                 // [2, E] int32 or int64

    float* out    = (float*)d_out;
    float* axw    = out;                               // [N, 128]
    float* ew     = out + (long)N_NODES * 128;         // [E, 128]
    float* scores = ew + (long)E_EDGES * 128;          // [E]

    float* xw;     cudaGetSymbolAddress((void**)&xw, g_xw);
    __half* axw_h; cudaGetSymbolAddress((void**)&axw_h, g_axw_h);

    // lazily created once (correctness call, pre-capture); reused thereafter.
    static cudaStream_t s1 = nullptr;
    static cudaEvent_t evF = nullptr, evJ = nullptr;
    if (!s1) {
        cudaStreamCreateWithFlags(&s1, cudaStreamNonBlocking);
        cudaEventCreateWithFlags(&evF, cudaEventDisableTiming);
        cudaEventCreateWithFlags(&evJ, cudaEventDisableTiming);
    }

    const int SMEM_XW = 256 * 256 + 32768;   // 98304  (KCH=2)
    const int SMEM_EW = 128 * 256 + 32768;   // 65536  (KCH=1)
    cudaFuncSetAttribute(gemm_kernel<2>,
                         cudaFuncAttributeMaxDynamicSharedMemorySize, SMEM_XW);
    cudaFuncSetAttribute(gemm_kernel<1>,
                         cudaFuncAttributeMaxDynamicSharedMemorySize, SMEM_EW);

    // ---- fork: ew GEMM on s1 (no dependencies) ----
    cudaEventRecord(evF, 0);
    cudaStreamWaitEvent(s1, evF, 0);
    gemm_kernel<1><<<304, 256, SMEM_EW, s1>>>(ea, we, ew, E_EDGES);

    // ---- s0 chain ----
    detect_idx_kernel<<<1, 32>>>(eidx);
    {
        int n4 = N_NODES * 128 / 4;
        zero4_kernel<<<(n4 + 255) / 256, 256>>>((float4*)axw, n4);
    }
    gemm_kernel<2><<<152, 256, SMEM_XW>>>(x, wn, xw, N_NODES);
    {
        long total = (long)E_EDGES * 32;
        scatter_kernel<<<(int)((total + 255) / 256), 256>>>(eidx, xw, axw);
    }
    {
        int n2 = N_NODES * 128 / 2;
        tohalf_kernel<<<(n2 + 255) / 256, 256>>>((const float2*)axw, (__half2*)axw_h, n2);
    }

    // ---- join + scores ----
    cudaEventRecord(evJ, s1);
    cudaStreamWaitEvent(0, evJ, 0);
    {
        long total = (long)E_EDGES * 32;
        scores_kernel<<<(int)((total + 255) / 256), 256>>>(
            eidx, axw_h, ew, tc, lw, scores);
    }
}

// round 13
// speedup vs baseline: 1.0577x; 1.0577x over previous
#include <cuda_runtime.h>
#include <cuda_fp16.h>
#include <cstdint>

#define N_NODES 100000
#define E_EDGES 640000

// ---------------------------------------------------------------------------
// Global scratch
// ---------------------------------------------------------------------------
__device__ float  g_xw[(size_t)N_NODES * 128];     // x @ Wn
__device__ __half g_axw_h[(size_t)N_NODES * 128];  // fp16 shadow of axw
__device__ int    g_idx64;                          // edge_index dtype flag

// ---------------------------------------------------------------------------
// Helpers
// ---------------------------------------------------------------------------
__device__ __forceinline__ uint32_t smem_u32(const void* p) {
    uint32_t a;
    asm("{ .reg .u64 t; cvta.to.shared.u64 t, %1; cvt.u32.u64 %0, t; }"
        : "=r"(a) : "l"(p));
    return a;
}

__device__ __forceinline__ void mma_f16(float* d, const uint32_t* a, const uint32_t* b) {
    asm volatile(
        "mma.sync.aligned.m16n8k16.row.col.f32.f16.f16.f32 "
        "{%0,%1,%2,%3}, {%4,%5,%6,%7}, {%8,%9}, {%0,%1,%2,%3};"
        : "+f"(d[0]), "+f"(d[1]), "+f"(d[2]), "+f"(d[3])
        : "r"(a[0]), "r"(a[1]), "r"(a[2]), "r"(a[3]), "r"(b[0]), "r"(b[1]));
}

__device__ __forceinline__ void ldsm_x4(uint32_t* r, uint32_t addr) {
    asm volatile("ldmatrix.sync.aligned.m8n8.x4.shared.b16 {%0,%1,%2,%3}, [%4];"
                 : "=r"(r[0]), "=r"(r[1]), "=r"(r[2]), "=r"(r[3]) : "r"(addr));
}
__device__ __forceinline__ void ldsm_x4t(uint32_t* r, uint32_t addr) {
    asm volatile("ldmatrix.sync.aligned.m8n8.x4.trans.shared.b16 {%0,%1,%2,%3}, [%4];"
                 : "=r"(r[0]), "=r"(r[1]), "=r"(r[2]), "=r"(r[3]) : "r"(addr));
}

__device__ __forceinline__ void cp_async16(uint32_t smem_dst, const void* gmem_src) {
    asm volatile("cp.async.ca.shared.global [%0], [%1], 16;"
                 :: "r"(smem_dst), "l"(gmem_src) : "memory");
}

// epilogue row helper
__device__ __forceinline__ int r0_expr(int wr, int lane) { return wr * 32 + (lane >> 2); }

// ---------------------------------------------------------------------------
// edge_index dtype detection (int32 vs int64)
// ---------------------------------------------------------------------------
__global__ void detect_idx_kernel(const void* __restrict__ eidx) {
    if (threadIdx.x == 0 && blockIdx.x == 0) {
        const unsigned long long* p = (const unsigned long long*)eidx;
        int ok = 1;
        #pragma unroll 1
        for (int i = 0; i < 64; i++)
            if (p[i] >= (unsigned long long)N_NODES) { ok = 0; break; }
        g_idx64 = ok;
    }
}

__device__ __forceinline__ long ld_idx(const void* __restrict__ p, long i) {
    if (g_idx64) return (long)((const long long*)p)[i];
    return (long)((const int*)p)[i];
}

__global__ void zero4_kernel(float4* __restrict__ p, int n4) {
    int i = blockIdx.x * blockDim.x + threadIdx.x;
    if (i < n4) p[i] = make_float4(0.f, 0.f, 0.f, 0.f);
}

// axw (fp32) -> fp16 shadow for low-traffic gathers
__global__ void tohalf_kernel(const float2* __restrict__ in, __half2* __restrict__ outp, int n2) {
    int i = blockIdx.x * blockDim.x + threadIdx.x;
    if (i < n2) {
        float2 v = in[i];
        outp[i] = __floats2half2_rn(v.x, v.y);
    }
}

// ---------------------------------------------------------------------------
// xw GEMM (R12-measured fastest): 64-row tiles, 2 CTAs/SM, plain epilogue.
// C[M x 128] = A[M x K] @ W[K x 128], K = KCH*128, fp16 single-pass.
// ---------------------------------------------------------------------------
template<int KCH>
__global__ __launch_bounds__(256, 2)
void gemm64_kernel(const float* __restrict__ A, const float* __restrict__ W,
                   float* __restrict__ C, int M) {
    constexpr int K = KCH * 128;
    constexpr uint32_t OFF_A = (uint32_t)K * 256;

    extern __shared__ __align__(128) char smem[];
    const uint32_t sb = smem_u32(smem);
    const int tid = threadIdx.x, lane = tid & 31, wid = tid >> 5;
    const int wr = wid & 1, wc = wid >> 1;

    for (int p = tid; p < K * 64; p += 256) {
        int k = p >> 6, n = (p & 63) * 2;
        float2 wv = *(const float2*)(W + (long)k * 128 + n);
        __half2 hp = __floats2half2_rn(wv.x, wv.y);
        uint32_t off = (uint32_t)k * 256 +
                       ((((uint32_t)n >> 3) ^ ((uint32_t)k & 7)) << 4) + ((n & 7) << 1);
        *(__half2*)(smem + off) = hp;
    }

    const int ntiles = (M + 63) >> 6;
    const int G = gridDim.x;
    float2 pref[16];

    auto prefetch = [&](int t, int kc) {
        #pragma unroll
        for (int i = 0; i < 16; i++) {
            int p = i * 256 + tid;
            int r = p >> 6, pc = p & 63;
            long row = (long)t * 64 + r;
            float2 v = make_float2(0.f, 0.f);
            if (row < M) v = __ldcs((const float2*)(A + row * (long)K + kc * 128 + pc * 2));
            pref[i] = v;
        }
    };
    auto store_buf = [&](int b) {
        #pragma unroll
        for (int i = 0; i < 16; i++) {
            int p = i * 256 + tid;
            int r = p >> 6, col = (p & 63) * 2;
            __half2 hp = __floats2half2_rn(pref[i].x, pref[i].y);
            uint32_t off = (uint32_t)r * 256 +
                           ((((uint32_t)col >> 3) ^ ((uint32_t)r & 7)) << 4) +
                           ((col & 7) << 1);
            *(__half2*)(smem + OFF_A + (uint32_t)b * 16384 + off) = hp;
        }
    };

    int tile = blockIdx.x;
    if (tile < ntiles) {
        prefetch(tile, 0);
        store_buf(0);
        int nt = tile, nkc = 1;
        if (KCH == 1) { nt = tile + G; nkc = 0; }
        if (nt < ntiles) prefetch(nt, nkc);
    }
    __syncthreads();

    int cur = 0;
    for (; tile < ntiles; tile += G) {
        float acc[2][4][4];
        #pragma unroll
        for (int m = 0; m < 2; m++)
            #pragma unroll
            for (int nb = 0; nb < 4; nb++)
                #pragma unroll
                for (int c = 0; c < 4; c++) acc[m][nb][c] = 0.f;

        for (int kc = 0; kc < KCH; kc++) {
            int nt1 = tile, nkc1 = kc + 1;
            if (nkc1 == KCH) { nkc1 = 0; nt1 = tile + G; }
            if (nt1 < ntiles) store_buf(cur ^ 1);
            int nt2 = nt1, nkc2 = nkc1 + 1;
            if (nkc2 == KCH) { nkc2 = 0; nt2 = nt1 + G; }
            if (nt2 < ntiles) prefetch(nt2, nkc2);

            const uint32_t abase = sb + OFF_A + (uint32_t)cur * 16384;
            #pragma unroll
            for (int s = 0; s < 8; s++) {
                uint32_t a[2][4];
                #pragma unroll
                for (int m = 0; m < 2; m++) {
                    uint32_t r = (uint32_t)(wr * 32 + m * 16 + (lane & 15));
                    uint32_t ch = (uint32_t)(s * 2 + (lane >> 4));
                    ldsm_x4(a[m], abase + r * 256 + (((ch ^ (r & 7)) << 4)));
                }
                uint32_t bh[2][4];
                #pragma unroll
                for (int p4 = 0; p4 < 2; p4++) {
                    uint32_t k = (uint32_t)(kc * 128 + s * 16 + (lane & 15));
                    uint32_t nch = (uint32_t)(wc * 4 + p4 * 2 + (lane >> 4));
                    ldsm_x4t(bh[p4], sb + k * 256 + (((nch ^ (k & 7)) << 4)));
                }
                #pragma unroll
                for (int m = 0; m < 2; m++)
                    #pragma unroll
                    for (int p4 = 0; p4 < 2; p4++)
                        #pragma unroll
                        for (int h = 0; h < 2; h++)
                            mma_f16(acc[m][p4 * 2 + h], a[m], &bh[p4][2 * h]);
            }
            if (kc < KCH - 1) { __syncthreads(); cur ^= 1; }
        }

        #pragma unroll
        for (int j = 0; j < 4; j++) {
            const int m = j >> 1, cp = (j & 1) * 2;
            const int r = wr * 32 + m * 16 + (lane >> 2) + ((j & 1) ? 8 : 0);
            long grow = (long)tile * 64 + r;
            if (grow < M) {
                float* crow = C + grow * 128 + wc * 32 + (lane & 3) * 2;
                #pragma unroll
                for (int nb = 0; nb < 4; nb++)
                    __stcs((float2*)(crow + nb * 8),
                           make_float2(acc[m][nb][cp], acc[m][nb][cp + 1]));
            }
        }
        __syncthreads();
        cur ^= 1;
    }
}

// ---------------------------------------------------------------------------
// ew GEMM + fused DistMult (R10-measured best): 128-row tiles, 1 CTA/SM,
// cp.async gather staging of 256 fp16 axw rows at tile start.
// Smem: [0,32K) W | +2x32K A bufs | +2x1K red | 256 rows x 272B gather
// ---------------------------------------------------------------------------
__global__ __launch_bounds__(256, 1)
void gemm_ew_kernel(const float* __restrict__ A, const float* __restrict__ W,
                    float* __restrict__ C, int M,
                    const void* __restrict__ eidx,
                    const __half* __restrict__ axw_h,
                    const float* __restrict__ tcl,
                    const float* __restrict__ lw,
                    float* __restrict__ scores) {
    constexpr uint32_t OFF_A   = 32768;
    constexpr uint32_t OFF_RED = OFF_A + 65536;
    constexpr uint32_t OFF_G   = OFF_RED + 2048;
    constexpr uint32_t GPITCH  = 272;

    extern __shared__ __align__(128) char smem[];
    const uint32_t sb = smem_u32(smem);
    const int tid = threadIdx.x, lane = tid & 31, wid = tid >> 5;
    const int wr = wid & 3, wc = wid >> 2;

    for (int p = tid; p < 128 * 64; p += 256) {
        int k = p >> 6, n = (p & 63) * 2;
        float2 wv = *(const float2*)(W + (long)k * 128 + n);
        __half2 hp = __floats2half2_rn(wv.x, wv.y);
        uint32_t off = (uint32_t)k * 256 +
                       ((((uint32_t)n >> 3) ^ ((uint32_t)k & 7)) << 4) + ((n & 7) << 1);
        *(__half2*)(smem + off) = hp;
    }

    const float lwv = lw[0];
    const int ntiles = (M + 127) >> 7;
    const int G = gridDim.x;
    float2 pref[32];

    auto prefetch = [&](int t) {
        #pragma unroll
        for (int i = 0; i < 32; i++) {
            int p = i * 256 + tid;
            int r = p >> 6, pc = p & 63;
            long row = (long)t * 128 + r;
            float2 v = make_float2(0.f, 0.f);
            if (row < M) v = __ldcs((const float2*)(A + row * 128l + pc * 2));
            pref[i] = v;
        }
    };
    auto store_buf = [&](int b) {
        #pragma unroll
        for (int i = 0; i < 32; i++) {
            int p = i * 256 + tid;
            int r = p >> 6, col = (p & 63) * 2;
            __half2 hp = __floats2half2_rn(pref[i].x, pref[i].y);
            uint32_t off = (uint32_t)r * 256 +
                           ((((uint32_t)col >> 3) ^ ((uint32_t)r & 7)) << 4) +
                           ((col & 7) << 1);
            *(__half2*)(smem + OFF_A + (uint32_t)b * 32768 + off) = hp;
        }
    };

    int tile = blockIdx.x;
    if (tile < ntiles) {
        prefetch(tile);
        store_buf(0);
        if (tile + G < ntiles) prefetch(tile + G);
    }
    __syncthreads();

    int cur = 0, rcur = 0;
    for (; tile < ntiles; tile += G) {
        // cp.async staging of this tile's 256 gather rows
        {
            long e = (long)tile * 128 + (tid & 127);
            long idx = ld_idx(eidx, (tid < 128) ? e : (long)E_EDGES + e);
            const char* srcp = (const char*)(axw_h + idx * 128);
            uint32_t dstp = sb + OFF_G + (uint32_t)tid * GPITCH;
            #pragma unroll
            for (int c = 0; c < 16; c++)
                cp_async16(dstp + c * 16, srcp + c * 16);
            asm volatile("cp.async.commit_group;" ::: "memory");
        }

        float acc[2][8][4];
        #pragma unroll
        for (int m = 0; m < 2; m++)
            #pragma unroll
            for (int nb = 0; nb < 8; nb++)
                #pragma unroll
                for (int c = 0; c < 4; c++) acc[m][nb][c] = 0.f;

        // stage successor tile; prefetch the one after
        if (tile + G < ntiles) store_buf(cur ^ 1);
        if (tile + 2 * G < ntiles) prefetch(tile + 2 * G);

        const uint32_t abase = sb + OFF_A + (uint32_t)cur * 32768;
        #pragma unroll
        for (int s = 0; s < 8; s++) {
            uint32_t a[2][4];
            #pragma unroll
            for (int m = 0; m < 2; m++) {
                uint32_t r = (uint32_t)(wr * 32 + m * 16 + (lane & 15));
                uint32_t ch = (uint32_t)(s * 2 + (lane >> 4));
                ldsm_x4(a[m], abase + r * 256 + (((ch ^ (r & 7)) << 4)));
            }
            uint32_t bh[4][4];
            #pragma unroll
            for (int p4 = 0; p4 < 4; p4++) {
                uint32_t k = (uint32_t)(s * 16 + (lane & 15));
                uint32_t nch = (uint32_t)(wc * 8 + p4 * 2 + (lane >> 4));
                ldsm_x4t(bh[p4], sb + k * 256 + (((nch ^ (k & 7)) << 4)));
            }
            #pragma unroll
            for (int m = 0; m < 2; m++)
                #pragma unroll
                for (int p4 = 0; p4 < 4; p4++)
                    #pragma unroll
                    for (int h = 0; h < 2; h++)
                        mma_f16(acc[m][p4 * 2 + h], a[m], &bh[p4][2 * h]);
        }

        asm volatile("cp.async.wait_group 0;" ::: "memory");
        __syncthreads();    // gather rows visible

        float* red = (float*)(smem + OFF_RED + (uint32_t)rcur * 1024);
        #pragma unroll
        for (int j = 0; j < 4; j++) {
            const int m = j >> 1, cp = (j & 1) * 2;
            const int r = r0_expr(wr, lane) + j * 8;
            long grow = (long)tile * 128 + r;
            if (grow < M) {
                float* crow = C + grow * 128 + wc * 64 + (lane & 3) * 2;
                const __half2* hq = (const __half2*)(smem + OFF_G + (uint32_t)r * GPITCH
                                                     + (uint32_t)wc * 128) + (lane & 3);
                const __half2* tq = (const __half2*)(smem + OFF_G
                                                     + (uint32_t)(128 + r) * GPITCH
                                                     + (uint32_t)wc * 128) + (lane & 3);
                float part = 0.f;
                #pragma unroll
                for (int nb = 0; nb < 8; nb++) {
                    float2 v = make_float2(acc[m][nb][cp], acc[m][nb][cp + 1]);
                    __stcs((float2*)(crow + nb * 8), v);
                    float2 h2 = __half22float2(hq[nb * 4]);
                    float2 t2 = __half22float2(tq[nb * 4]);
                    part = fmaf(v.x * h2.x, t2.x, part);
                    part = fmaf(v.y * h2.y, t2.y, part);
                }
                part += __shfl_xor_sync(0xFFFFFFFFu, part, 1);
                part += __shfl_xor_sync(0xFFFFFFFFu, part, 2);
                if ((lane & 3) == 0) red[wc * 128 + r] = part;
            }
        }
        __syncthreads();
        if (tid < 128) {
            long g2 = (long)tile * 128 + tid;
            scores[g2] = (red[tid] + red[128 + tid]) * tcl[g2] * lwv;
        }
        cur ^= 1; rcur ^= 1;
    }
}

// ---------------------------------------------------------------------------
// Scatter-add: axw[dst] += xw[src]  (warp per edge, vector reduction)
// ---------------------------------------------------------------------------
__global__ void scatter_kernel(const void* __restrict__ eidx,
                               const float* __restrict__ xw,
                               float* __restrict__ axw) {
    long t = (long)blockIdx.x * blockDim.x + threadIdx.x;
    if (t >= (long)E_EDGES * 32) return;
    long e = t >> 5;
    int  q = (int)(t & 31) * 4;
    long src = ld_idx(eidx, e);
    long dst = ld_idx(eidx, (long)E_EDGES + e);
    float4 v = *(const float4*)&xw[src * 128 + q];
    float* o = &axw[dst * 128 + q];
    asm volatile("red.global.add.v4.f32 [%0], {%1, %2, %3, %4};"
                 :: "l"(o), "f"(v.x), "f"(v.y), "f"(v.z), "f"(v.w) : "memory");
}

// ---------------------------------------------------------------------------
// Launch (serial chain — stream overlap proven ineffective under capture)
// ---------------------------------------------------------------------------
extern "C" void kernel_launch(void* const* d_in, const int* in_sizes, int n_in,
                              void* d_out, int out_size) {
    const float* x    = (const float*)d_in[0];   // [N, 256]
    const float* ea   = (const float*)d_in[1];   // [E, 128]
    const float* tc   = (const float*)d_in[2];   // [E]
    const float* wn   = (const float*)d_in[3];   // [256, 128]
    const float* we   = (const float*)d_in[4];   // [128, 128]
    const float* lw   = (const float*)d_in[5];   // [1]
    const void*  eidx = d_in[6];                 // [2, E] int32 or int64

    float* out    = (float*)d_out;
    float* axw    = out;                               // [N, 128]
    float* ew     = out + (long)N_NODES * 128;         // [E, 128]
    float* scores = ew + (long)E_EDGES * 128;          // [E]

    float* xw;     cudaGetSymbolAddress((void**)&xw, g_xw);
    __half* axw_h; cudaGetSymbolAddress((void**)&axw_h, g_axw_h);

    const int SMEM_XW = 256 * 256 + 32768;                      // 98304
    const int SMEM_EW = 32768 + 65536 + 2048 + 256 * 272;       // 169984
    cudaFuncSetAttribute(gemm64_kernel<2>,
                         cudaFuncAttributeMaxDynamicSharedMemorySize, SMEM_XW);
    cudaFuncSetAttribute(gemm_ew_kernel,
                         cudaFuncAttributeMaxDynamicSharedMemorySize, SMEM_EW);

    // 1) dtype detection
    detect_idx_kernel<<<1, 32>>>(eidx);

    // 2) zero axw (accumulated via reductions)
    {
        int n4 = N_NODES * 128 / 4;
        zero4_kernel<<<(n4 + 255) / 256, 256>>>((float4*)axw, n4);
    }

    // 3) xw = x @ Wn  (64-row tiles, 2 CTAs/SM — measured 43us in R12)
    gemm64_kernel<2><<<304, 256, SMEM_XW>>>(x, wn, xw, N_NODES);

    // 4) axw = segment_sum(xw[src], dst)
    {
        long total = (long)E_EDGES * 32;
        scatter_kernel<<<(int)((total + 255) / 256), 256>>>(eidx, xw, axw);
    }

    // 5) fp16 shadow of axw (feeds smem gather staging)
    {
        int n2 = N_NODES * 128 / 2;
        tohalf_kernel<<<(n2 + 255) / 256, 256>>>((const float2*)axw, (__half2*)axw_h, n2);
    }

    // 6) ew = edge_attr @ We + fused DistMult (128-row tiles, cp.async gathers)
    gemm_ew_kernel<<<152, 256, SMEM_EW>>>(ea, we, ew, E_EDGES, eidx, axw_h,
                                          tc, lw, scores);
}

// round 14
// speedup vs baseline: 1.0934x; 1.0337x over previous
#include <cuda_runtime.h>
#include <cuda_fp16.h>
#include <cstdint>

#define N_NODES 100000
#define E_EDGES 640000

// ---------------------------------------------------------------------------
// Global scratch
// ---------------------------------------------------------------------------
__device__ __half g_xw_h[(size_t)N_NODES * 128];   // x @ Wn (fp16 storage)
__device__ __half g_axw_h[(size_t)N_NODES * 128];  // fp16 shadow of axw
__device__ int    g_idx64;                          // edge_index dtype flag

// ---------------------------------------------------------------------------
// Helpers
// ---------------------------------------------------------------------------
__device__ __forceinline__ uint32_t smem_u32(const void* p) {
    uint32_t a;
    asm("{ .reg .u64 t; cvta.to.shared.u64 t, %1; cvt.u32.u64 %0, t; }"
        : "=r"(a) : "l"(p));
    return a;
}

__device__ __forceinline__ void mma_f16(float* d, const uint32_t* a, const uint32_t* b) {
    asm volatile(
        "mma.sync.aligned.m16n8k16.row.col.f32.f16.f16.f32 "
        "{%0,%1,%2,%3}, {%4,%5,%6,%7}, {%8,%9}, {%0,%1,%2,%3};"
        : "+f"(d[0]), "+f"(d[1]), "+f"(d[2]), "+f"(d[3])
        : "r"(a[0]), "r"(a[1]), "r"(a[2]), "r"(a[3]), "r"(b[0]), "r"(b[1]));
}

__device__ __forceinline__ void ldsm_x4(uint32_t* r, uint32_t addr) {
    asm volatile("ldmatrix.sync.aligned.m8n8.x4.shared.b16 {%0,%1,%2,%3}, [%4];"
                 : "=r"(r[0]), "=r"(r[1]), "=r"(r[2]), "=r"(r[3]) : "r"(addr));
}
__device__ __forceinline__ void ldsm_x4t(uint32_t* r, uint32_t addr) {
    asm volatile("ldmatrix.sync.aligned.m8n8.x4.trans.shared.b16 {%0,%1,%2,%3}, [%4];"
                 : "=r"(r[0]), "=r"(r[1]), "=r"(r[2]), "=r"(r[3]) : "r"(addr));
}

__device__ __forceinline__ void cp_async16(uint32_t smem_dst, const void* gmem_src) {
    asm volatile("cp.async.ca.shared.global [%0], [%1], 16;"
                 :: "r"(smem_dst), "l"(gmem_src) : "memory");
}

// epilogue row helper
__device__ __forceinline__ int r0_expr(int wr, int lane) { return wr * 32 + (lane >> 2); }

// ---------------------------------------------------------------------------
// edge_index dtype detection (int32 vs int64)
// ---------------------------------------------------------------------------
__global__ void detect_idx_kernel(const void* __restrict__ eidx) {
    if (threadIdx.x == 0 && blockIdx.x == 0) {
        const unsigned long long* p = (const unsigned long long*)eidx;
        int ok = 1;
        #pragma unroll 1
        for (int i = 0; i < 64; i++)
            if (p[i] >= (unsigned long long)N_NODES) { ok = 0; break; }
        g_idx64 = ok;
    }
}

__device__ __forceinline__ long ld_idx(const void* __restrict__ p, long i) {
    if (g_idx64) return (long)((const long long*)p)[i];
    return (long)((const int*)p)[i];
}

// axw (fp32) -> fp16 shadow for low-traffic gathers
__global__ void tohalf_kernel(const float2* __restrict__ in, __half2* __restrict__ outp, int n2) {
    int i = blockIdx.x * blockDim.x + threadIdx.x;
    if (i < n2) {
        float2 v = in[i];
        outp[i] = __floats2half2_rn(v.x, v.y);
    }
}

// ---------------------------------------------------------------------------
// xw GEMM: 64-row tiles, 2 CTAs/SM, fp16 output, fused axw-zero prologue.
// C[M x 128] (fp16) = A[M x 256] @ W[256 x 128], fp16 single-pass.
// ---------------------------------------------------------------------------
__global__ __launch_bounds__(256, 2)
void gemm_xw_kernel(const float* __restrict__ A, const float* __restrict__ W,
                    __half* __restrict__ C, int M,
                    float4* __restrict__ zbuf, int zn4) {
    constexpr int K = 256;
    constexpr int KCH = 2;
    constexpr uint32_t OFF_A = (uint32_t)K * 256;

    extern __shared__ __align__(128) char smem[];
    const uint32_t sb = smem_u32(smem);
    const int tid = threadIdx.x, lane = tid & 31, wid = tid >> 5;
    const int wr = wid & 1, wc = wid >> 1;

    // fused zero of the axw output region (ordering vs scatter = kernel boundary)
    {
        const float4 z = make_float4(0.f, 0.f, 0.f, 0.f);
        int stride = gridDim.x * 256;
        for (int i = blockIdx.x * 256 + tid; i < zn4; i += stride) zbuf[i] = z;
    }

    for (int p = tid; p < K * 64; p += 256) {
        int k = p >> 6, n = (p & 63) * 2;
        float2 wv = *(const float2*)(W + (long)k * 128 + n);
        __half2 hp = __floats2half2_rn(wv.x, wv.y);
        uint32_t off = (uint32_t)k * 256 +
                       ((((uint32_t)n >> 3) ^ ((uint32_t)k & 7)) << 4) + ((n & 7) << 1);
        *(__half2*)(smem + off) = hp;
    }

    const int ntiles = (M + 63) >> 6;
    const int G = gridDim.x;
    float2 pref[16];

    auto prefetch = [&](int t, int kc) {
        #pragma unroll
        for (int i = 0; i < 16; i++) {
            int p = i * 256 + tid;
            int r = p >> 6, pc = p & 63;
            long row = (long)t * 64 + r;
            float2 v = make_float2(0.f, 0.f);
            if (row < M) v = __ldcs((const float2*)(A + row * (long)K + kc * 128 + pc * 2));
            pref[i] = v;
        }
    };
    auto store_buf = [&](int b) {
        #pragma unroll
        for (int i = 0; i < 16; i++) {
            int p = i * 256 + tid;
            int r = p >> 6, col = (p & 63) * 2;
            __half2 hp = __floats2half2_rn(pref[i].x, pref[i].y);
            uint32_t off = (uint32_t)r * 256 +
                           ((((uint32_t)col >> 3) ^ ((uint32_t)r & 7)) << 4) +
                           ((col & 7) << 1);
            *(__half2*)(smem + OFF_A + (uint32_t)b * 16384 + off) = hp;
        }
    };

    int tile = blockIdx.x;
    if (tile < ntiles) {
        prefetch(tile, 0);
        store_buf(0);
        prefetch(tile, 1);
    }
    __syncthreads();

    int cur = 0;
    for (; tile < ntiles; tile += G) {
        float acc[2][4][4];
        #pragma unroll
        for (int m = 0; m < 2; m++)
            #pragma unroll
            for (int nb = 0; nb < 4; nb++)
                #pragma unroll
                for (int c = 0; c < 4; c++) acc[m][nb][c] = 0.f;

        for (int kc = 0; kc < KCH; kc++) {
            int nt1 = tile, nkc1 = kc + 1;
            if (nkc1 == KCH) { nkc1 = 0; nt1 = tile + G; }
            if (nt1 < ntiles) store_buf(cur ^ 1);
            int nt2 = nt1, nkc2 = nkc1 + 1;
            if (nkc2 == KCH) { nkc2 = 0; nt2 = nt1 + G; }
            if (nt2 < ntiles) prefetch(nt2, nkc2);

            const uint32_t abase = sb + OFF_A + (uint32_t)cur * 16384;
            #pragma unroll
            for (int s = 0; s < 8; s++) {
                uint32_t a[2][4];
                #pragma unroll
                for (int m = 0; m < 2; m++) {
                    uint32_t r = (uint32_t)(wr * 32 + m * 16 + (lane & 15));
                    uint32_t ch = (uint32_t)(s * 2 + (lane >> 4));
                    ldsm_x4(a[m], abase + r * 256 + (((ch ^ (r & 7)) << 4)));
                }
                uint32_t bh[2][4];
                #pragma unroll
                for (int p4 = 0; p4 < 2; p4++) {
                    uint32_t k = (uint32_t)(kc * 128 + s * 16 + (lane & 15));
                    uint32_t nch = (uint32_t)(wc * 4 + p4 * 2 + (lane >> 4));
                    ldsm_x4t(bh[p4], sb + k * 256 + (((nch ^ (k & 7)) << 4)));
                }
                #pragma unroll
                for (int m = 0; m < 2; m++)
                    #pragma unroll
                    for (int p4 = 0; p4 < 2; p4++)
                        #pragma unroll
                        for (int h = 0; h < 2; h++)
                            mma_f16(acc[m][p4 * 2 + h], a[m], &bh[p4][2 * h]);
            }
            if (kc < KCH - 1) { __syncthreads(); cur ^= 1; }
        }

        // epilogue: fp16 store (halved write traffic)
        #pragma unroll
        for (int j = 0; j < 4; j++) {
            const int m = j >> 1, cp = (j & 1) * 2;
            const int r = wr * 32 + m * 16 + (lane >> 2) + ((j & 1) ? 8 : 0);
            long grow = (long)tile * 64 + r;
            if (grow < M) {
                __half* crow = C + grow * 128 + wc * 32 + (lane & 3) * 2;
                #pragma unroll
                for (int nb = 0; nb < 4; nb++)
                    *(__half2*)(crow + nb * 8) =
                        __floats2half2_rn(acc[m][nb][cp], acc[m][nb][cp + 1]);
            }
        }
        __syncthreads();
        cur ^= 1;
    }
}

// ---------------------------------------------------------------------------
// ew GEMM + fused DistMult: 128-row tiles, 1 CTA/SM, cp.async gather staging.
// Smem: [0,32K) W | +2x32K A bufs | +2x1K red | 256 rows x 272B gather
// ---------------------------------------------------------------------------
__global__ __launch_bounds__(256, 1)
void gemm_ew_kernel(const float* __restrict__ A, const float* __restrict__ W,
                    float* __restrict__ C, int M,
                    const void* __restrict__ eidx,
                    const __half* __restrict__ axw_h,
                    const float* __restrict__ tcl,
                    const float* __restrict__ lw,
                    float* __restrict__ scores) {
    constexpr uint32_t OFF_A   = 32768;
    constexpr uint32_t OFF_RED = OFF_A + 65536;
    constexpr uint32_t OFF_G   = OFF_RED + 2048;
    constexpr uint32_t GPITCH  = 272;

    extern __shared__ __align__(128) char smem[];
    const uint32_t sb = smem_u32(smem);
    const int tid = threadIdx.x, lane = tid & 31, wid = tid >> 5;
    const int wr = wid & 3, wc = wid >> 2;

    for (int p = tid; p < 128 * 64; p += 256) {
        int k = p >> 6, n = (p & 63) * 2;
        float2 wv = *(const float2*)(W + (long)k * 128 + n);
        __half2 hp = __floats2half2_rn(wv.x, wv.y);
        uint32_t off = (uint32_t)k * 256 +
                       ((((uint32_t)n >> 3) ^ ((uint32_t)k & 7)) << 4) + ((n & 7) << 1);
        *(__half2*)(smem + off) = hp;
    }

    const float lwv = lw[0];
    const int ntiles = (M + 127) >> 7;
    const int G = gridDim.x;
    float2 pref[32];

    auto prefetch = [&](int t) {
        #pragma unroll
        for (int i = 0; i < 32; i++) {
            int p = i * 256 + tid;
            int r = p >> 6, pc = p & 63;
            long row = (long)t * 128 + r;
            float2 v = make_float2(0.f, 0.f);
            if (row < M) v = __ldcs((const float2*)(A + row * 128l + pc * 2));
            pref[i] = v;
        }
    };
    auto store_buf = [&](int b) {
        #pragma unroll
        for (int i = 0; i < 32; i++) {
            int p = i * 256 + tid;
            int r = p >> 6, col = (p & 63) * 2;
            __half2 hp = __floats2half2_rn(pref[i].x, pref[i].y);
            uint32_t off = (uint32_t)r * 256 +
                           ((((uint32_t)col >> 3) ^ ((uint32_t)r & 7)) << 4) +
                           ((col & 7) << 1);
            *(__half2*)(smem + OFF_A + (uint32_t)b * 32768 + off) = hp;
        }
    };

    int tile = blockIdx.x;
    if (tile < ntiles) {
        prefetch(tile);
        store_buf(0);
        if (tile + G < ntiles) prefetch(tile + G);
    }
    __syncthreads();

    int cur = 0, rcur = 0;
    for (; tile < ntiles; tile += G) {
        // cp.async staging of this tile's 256 gather rows
        {
            long e = (long)tile * 128 + (tid & 127);
            long idx = ld_idx(eidx, (tid < 128) ? e : (long)E_EDGES + e);
            const char* srcp = (const char*)(axw_h + idx * 128);
            uint32_t dstp = sb + OFF_G + (uint32_t)tid * GPITCH;
            #pragma unroll
            for (int c = 0; c < 16; c++)
                cp_async16(dstp + c * 16, srcp + c * 16);
            asm volatile("cp.async.commit_group;" ::: "memory");
        }

        float acc[2][8][4];
        #pragma unroll
        for (int m = 0; m < 2; m++)
            #pragma unroll
            for (int nb = 0; nb < 8; nb++)
                #pragma unroll
                for (int c = 0; c < 4; c++) acc[m][nb][c] = 0.f;

        if (tile + G < ntiles) store_buf(cur ^ 1);
        if (tile + 2 * G < ntiles) prefetch(tile + 2 * G);

        const uint32_t abase = sb + OFF_A + (uint32_t)cur * 32768;
        #pragma unroll
        for (int s = 0; s < 8; s++) {
            uint32_t a[2][4];
            #pragma unroll
            for (int m = 0; m < 2; m++) {
                uint32_t r = (uint32_t)(wr * 32 + m * 16 + (lane & 15));
                uint32_t ch = (uint32_t)(s * 2 + (lane >> 4));
                ldsm_x4(a[m], abase + r * 256 + (((ch ^ (r & 7)) << 4)));
            }
            uint32_t bh[4][4];
            #pragma unroll
            for (int p4 = 0; p4 < 4; p4++) {
                uint32_t k = (uint32_t)(s * 16 + (lane & 15));
                uint32_t nch = (uint32_t)(wc * 8 + p4 * 2 + (lane >> 4));
                ldsm_x4t(bh[p4], sb + k * 256 + (((nch ^ (k & 7)) << 4)));
            }
            #pragma unroll
            for (int m = 0; m < 2; m++)
                #pragma unroll
                for (int p4 = 0; p4 < 4; p4++)
                    #pragma unroll
                    for (int h = 0; h < 2; h++)
                        mma_f16(acc[m][p4 * 2 + h], a[m], &bh[p4][2 * h]);
        }

        asm volatile("cp.async.wait_group 0;" ::: "memory");
        __syncthreads();

        float* red = (float*)(smem + OFF_RED + (uint32_t)rcur * 1024);
        #pragma unroll
        for (int j = 0; j < 4; j++) {
            const int m = j >> 1, cp = (j & 1) * 2;
            const int r = r0_expr(wr, lane) + j * 8;
            long grow = (long)tile * 128 + r;
            if (grow < M) {
                float* crow = C + grow * 128 + wc * 64 + (lane & 3) * 2;
                const __half2* hq = (const __half2*)(smem + OFF_G + (uint32_t)r * GPITCH
                                                     + (uint32_t)wc * 128) + (lane & 3);
                const __half2* tq = (const __half2*)(smem + OFF_G
                                                     + (uint32_t)(128 + r) * GPITCH
                                                     + (uint32_t)wc * 128) + (lane & 3);
                float part = 0.f;
                #pragma unroll
                for (int nb = 0; nb < 8; nb++) {
                    float2 v = make_float2(acc[m][nb][cp], acc[m][nb][cp + 1]);
                    __stcs((float2*)(crow + nb * 8), v);
                    float2 h2 = __half22float2(hq[nb * 4]);
                    float2 t2 = __half22float2(tq[nb * 4]);
                    part = fmaf(v.x * h2.x, t2.x, part);
                    part = fmaf(v.y * h2.y, t2.y, part);
                }
                part += __shfl_xor_sync(0xFFFFFFFFu, part, 1);
                part += __shfl_xor_sync(0xFFFFFFFFu, part, 2);
                if ((lane & 3) == 0) red[wc * 128 + r] = part;
            }
        }
        __syncthreads();
        if (tid < 128) {
            long g2 = (long)tile * 128 + tid;
            scores[g2] = (red[tid] + red[128 + tid]) * tcl[g2] * lwv;
        }
        cur ^= 1; rcur ^= 1;
    }
}

// ---------------------------------------------------------------------------
// Scatter-add: axw[dst] += fp16 xw[src]  (warp per edge, halved read bytes)
// ---------------------------------------------------------------------------
__global__ void scatter_kernel(const void* __restrict__ eidx,
                               const __half* __restrict__ xwh,
                               float* __restrict__ axw) {
    long t = (long)blockIdx.x * blockDim.x + threadIdx.x;
    if (t >= (long)E_EDGES * 32) return;
    long e = t >> 5;
    int  q = (int)(t & 31) * 4;
    long src = ld_idx(eidx, e);
    long dst = ld_idx(eidx, (long)E_EDGES + e);
    uint2 raw = *(const uint2*)(xwh + src * 128 + q);
    float2 v0 = __half22float2(*(__half2*)&raw.x);
    float2 v1 = __half22float2(*(__half2*)&raw.y);
    float* o = &axw[dst * 128 + q];
    asm volatile("red.global.add.v4.f32 [%0], {%1, %2, %3, %4};"
                 :: "l"(o), "f"(v0.x), "f"(v0.y), "f"(v1.x), "f"(v1.y) : "memory");
}

// ---------------------------------------------------------------------------
// Launch
// ---------------------------------------------------------------------------
extern "C" void kernel_launch(void* const* d_in, const int* in_sizes, int n_in,
                              void* d_out, int out_size) {
    const float* x    = (const float*)d_in[0];   // [N, 256]
    const float* ea   = (const float*)d_in[1];   // [E, 128]
    const float* tc   = (const float*)d_in[2];   // [E]
    const float* wn   = (const float*)d_in[3];   // [256, 128]
    const float* we   = (const float*)d_in[4];   // [128, 128]
    const float* lw   = (const float*)d_in[5];   // [1]
    const void*  eidx = d_in[6];                 // [2, E] int32 or int64

    float* out    = (float*)d_out;
    float* axw    = out;                               // [N, 128]
    float* ew     = out + (long)N_NODES * 128;         // [E, 128]
    float* scores = ew + (long)E_EDGES * 128;          // [E]

    __half* xwh;   cudaGetSymbolAddress((void**)&xwh, g_xw_h);
    __half* axw_h; cudaGetSymbolAddress((void**)&axw_h, g_axw_h);

    const int SMEM_XW = 256 * 256 + 32768;                      // 98304
    const int SMEM_EW = 32768 + 65536 + 2048 + 256 * 272;       // 169984
    cudaFuncSetAttribute(gemm_xw_kernel,
                         cudaFuncAttributeMaxDynamicSharedMemorySize, SMEM_XW);
    cudaFuncSetAttribute(gemm_ew_kernel,
                         cudaFuncAttributeMaxDynamicSharedMemorySize, SMEM_EW);

    // 1) dtype detection
    detect_idx_kernel<<<1, 32>>>(eidx);

    // 2) xw = x @ Wn (fp16 out) + fused zero of axw
    gemm_xw_kernel<<<304, 256, SMEM_XW>>>(x, wn, xwh, N_NODES,
                                          (float4*)axw, N_NODES * 128 / 4);

    // 3) axw = segment_sum(xw[src], dst)  (fp16 reads, fp32 accumulation)
    {
        long total = (long)E_EDGES * 32;
        scatter_kernel<<<(int)((total + 255) / 256), 256>>>(eidx, xwh, axw);
    }

    // 4) fp16 shadow of axw (feeds smem gather staging)
    {
        int n2 = N_NODES * 128 / 2;
        tohalf_kernel<<<(n2 + 255) / 256, 256>>>((const float2*)axw, (__half2*)axw_h, n2);
    }

    // 5) ew = edge_attr @ We + fused DistMult (128-row tiles, cp.async gathers)
    gemm_ew_kernel<<<152, 256, SMEM_EW>>>(ea, we, ew, E_EDGES, eidx, axw_h,
                                          tc, lw, scores);
}